// round 6
// baseline (speedup 1.0000x reference)
#include <cuda_runtime.h>
#include <cstdint>

#define BATCH 64
#define SEQ   1024
#define DIN   256
#define UNITS 512

__device__ __forceinline__ void fma2(unsigned long long& d, unsigned long long a,
                                     unsigned long long b) {
    asm("fma.rn.f32x2 %0, %1, %2, %0;" : "+l"(d) : "l"(a), "l"(b));
}
__device__ __forceinline__ unsigned long long pack2(float x, float y) {
    unsigned long long r;
    asm("mov.b64 %0, {%1, %2};" : "=l"(r) : "f"(x), "f"(y));
    return r;
}
__device__ __forceinline__ float sum2(unsigned long long p) {
    float lo, hi;
    asm("mov.b64 {%0, %1}, %2;" : "=f"(lo), "=f"(hi) : "l"(p));
    return lo + hi;
}

// ================= xW GEMM: C[65536,512] = X[65536,256] @ W[256,512] ==========
#define GM_TM 128
#define GM_TN 128
#define GM_TK 16

__global__ void __launch_bounds__(256) xw_gemm_kernel(const float* __restrict__ X,
                                                      const float* __restrict__ W,
                                                      float* __restrict__ C) {
    __shared__ float As[GM_TK][GM_TM + 4];   // transposed: As[k][m]
    __shared__ float Bs[GM_TK][GM_TN + 4];

    const int tid = threadIdx.x;
    const int bm = blockIdx.y * GM_TM;
    const int bn = blockIdx.x * GM_TN;
    const int tx = tid & 15;
    const int ty = tid >> 4;

    unsigned long long acc2[8][4];           // [m][n-pair], packed f32x2
#pragma unroll
    for (int i = 0; i < 8; i++)
#pragma unroll
        for (int j = 0; j < 4; j++) acc2[i][j] = 0ull;

    const int arow = tid >> 2;
    const int acol = (tid & 3) * 4;
    const int brow = tid >> 5;
    const int bcol = (tid & 31) * 4;

    for (int k0 = 0; k0 < DIN; k0 += GM_TK) {
#pragma unroll
        for (int p = 0; p < 2; p++) {
            float4 v = *(const float4*)&X[(size_t)(bm + arow + p * 64) * DIN + k0 + acol];
            As[acol + 0][arow + p * 64] = v.x;
            As[acol + 1][arow + p * 64] = v.y;
            As[acol + 2][arow + p * 64] = v.z;
            As[acol + 3][arow + p * 64] = v.w;
        }
#pragma unroll
        for (int p = 0; p < 2; p++) {
            *(float4*)&Bs[brow + p * 8][bcol] =
                *(const float4*)&W[(size_t)(k0 + brow + p * 8) * UNITS + bn + bcol];
        }
        __syncthreads();

#pragma unroll
        for (int kk = 0; kk < GM_TK; kk++) {
            float a[8];
            *(float4*)&a[0] = *(const float4*)&As[kk][ty * 8];
            *(float4*)&a[4] = *(const float4*)&As[kk][ty * 8 + 4];
            unsigned long long bp[4];
            *(ulonglong2*)&bp[0] = *(const ulonglong2*)&Bs[kk][tx * 8];
            *(ulonglong2*)&bp[2] = *(const ulonglong2*)&Bs[kk][tx * 8 + 4];
#pragma unroll
            for (int i = 0; i < 8; i++) {
                const unsigned long long av = pack2(a[i], a[i]);
                fma2(acc2[i][0], av, bp[0]);
                fma2(acc2[i][1], av, bp[1]);
                fma2(acc2[i][2], av, bp[2]);
                fma2(acc2[i][3], av, bp[3]);
            }
        }
        __syncthreads();
    }

#pragma unroll
    for (int i = 0; i < 8; i++) {
        size_t row = (size_t)(bm + ty * 8 + i) * UNITS + bn + tx * 8;
        ulonglong2 v0, v1;
        v0.x = acc2[i][0]; v0.y = acc2[i][1];
        v1.x = acc2[i][2]; v1.y = acc2[i][3];
        *(ulonglong2*)&C[row]     = v0;
        *(ulonglong2*)&C[row + 4] = v1;
    }
}

// ================= LTC scan: clusters of 8, per-slice mbarriers ==============
// Cluster c owns batches [4c,4c+4). Rank s owns units [64s,64s+64).
// 512 threads = 16 warps: warp wid -> k-slice kq=wid&7 (k in [64kq,64kq+64)),
// u-half uh=wid>>3. Lane owns 1 unit, 4 batches. U: 32 packed regs/thread.
// Exchange: 7x 1KB cp.async.bulk to peers; per-slice mbar (8 per buffer);
// consuming warps wait only their slice and re-arm it themselves.
#define CLUSTER_SZ 8
#define SCAN_CTAS 128
#define SLICE_BYTES 1024

__device__ __forceinline__ void cluster_sync_() {
    asm volatile("barrier.cluster.arrive.aligned;" ::: "memory");
    asm volatile("barrier.cluster.wait.aligned;"   ::: "memory");
}
__device__ __forceinline__ uint32_t mapa_u32(uint32_t addr, int rank) {
    uint32_t r;
    asm("mapa.shared::cluster.u32 %0, %1, %2;" : "=r"(r) : "r"(addr), "r"(rank));
    return r;
}
__device__ __forceinline__ void mbar_init(uint32_t mbar, uint32_t count) {
    asm volatile("mbarrier.init.shared.b64 [%0], %1;" :: "r"(mbar), "r"(count) : "memory");
}
__device__ __forceinline__ void mbar_expect_tx(uint32_t mbar, uint32_t bytes) {
    asm volatile("mbarrier.arrive.expect_tx.shared.b64 _, [%0], %1;"
                 :: "r"(mbar), "r"(bytes) : "memory");
}
__device__ __forceinline__ void mbar_wait(uint32_t mbar, uint32_t parity) {
    asm volatile(
        "{\n\t"
        ".reg .pred P1;\n\t"
        "WAIT_LOOP_%=:\n\t"
        "mbarrier.try_wait.parity.acquire.cta.shared::cta.b64 P1, [%0], %1, 0x989680;\n\t"
        "@P1 bra.uni WAIT_DONE_%=;\n\t"
        "bra.uni WAIT_LOOP_%=;\n\t"
        "WAIT_DONE_%=:\n\t"
        "}"
        :: "r"(mbar), "r"(parity) : "memory");
}
__device__ __forceinline__ void bulk_s2s(uint32_t dst_cluster, uint32_t src_cta,
                                         uint32_t bytes, uint32_t mbar_cluster) {
    asm volatile(
        "cp.async.bulk.shared::cluster.shared::cta.mbarrier::complete_tx::bytes "
        "[%0], [%1], %2, [%3];"
        :: "r"(dst_cluster), "r"(src_cta), "r"(bytes), "r"(mbar_cluster) : "memory");
}
__device__ __forceinline__ void fence_async_() {
    asm volatile("fence.proxy.async.shared::cta;" ::: "memory");
}

__global__ void __launch_bounds__(512, 1) __cluster_dims__(CLUSTER_SZ, 1, 1)
ltc_scan_kernel(const float* __restrict__ U,
                const float* __restrict__ bias,
                const float* __restrict__ tau,
                float* out) {
    __shared__ __align__(128) float hs[2][8][4][64];   // [buf][slice][batch][u_local]
    __shared__ float ps[8][4][68];                     // k-split partials [kq][b][u_local]
    __shared__ __align__(8) unsigned long long mbar[2][8];

    const int tid = threadIdx.x;
    const int wid = tid >> 5;               // 0..15
    const int l   = tid & 31;
    const int kq  = wid & 7;                // k-slice (reads hs[.][kq][.][.])
    const int uh  = wid >> 3;               // u-half
    const int cta = blockIdx.x;
    const int s   = cta & 7;                // cluster rank = unit slice
    const int b0  = (cta >> 3) * 4;
    const int ulocal = uh * 32 + l;         // 0..63: this thread's unit in slice
    const int ug  = s * 64 + ulocal;        // global unit for compute mapping

    // ---- U column in packed registers: Urp[p] = {U[k][ug], U[k+1][ug]}, k=kq*64+2p
    unsigned long long Urp[32];
#pragma unroll
    for (int p = 0; p < 32; p++) {
        const int k = kq * 64 + 2 * p;
        Urp[p] = pack2(U[(size_t)k * UNITS + ug], U[(size_t)(k + 1) * UNITS + ug]);
    }

    // ---- epilogue mapping: tid<256 -> (batch eb, unit eul) ----
    const int eb  = (tid >> 6) & 3;
    const int eul = tid & 63;
    const int eu  = s * 64 + eul;
    const float invt = 1.0f / tau[eu];
    const float aa   = 1.0f - invt;
    const float bi   = bias[eu];
    float* orow = out + (size_t)(b0 + eb) * SEQ * UNITS + eu;

    // ---- zero h0 buffer ----
    for (int i = tid; i < 8 * 4 * 64; i += 512) ((float*)hs[0])[i] = 0.0f;

    const uint32_t mbar_base = (uint32_t)__cvta_generic_to_shared(&mbar[0][0]);
    const uint32_t slice0 = (uint32_t)__cvta_generic_to_shared(&hs[0][s][0][0]);
    const uint32_t slice1 = (uint32_t)__cvta_generic_to_shared(&hs[1][s][0][0]);

    if (tid < 16) {                          // (buf = tid>>3, slice = tid&7)
        const int sl = tid & 7;
        const uint32_t mb = mbar_base + (uint32_t)tid * 8;
        if (sl != s) {                       // own slice never arrives via DMA
            mbar_init(mb, 1);
            mbar_expect_tx(mb, SLICE_BYTES);
        }
    }
    __syncthreads();
    cluster_sync_();                         // mbars + h0 visible cluster-wide

    float xw = (tid < 256) ? __ldg(orow) : 0.0f;   // prefetch xW for t=0
    int ph0 = 0, ph1 = 0;
    const uint32_t my_mb0 = mbar_base + (uint32_t)kq * 8;        // buffer0, slice kq
    const uint32_t my_mb1 = mbar_base + (uint32_t)(8 + kq) * 8;  // buffer1, slice kq

    for (int t = 0; t < SEQ; t++) {
        const int cur = t & 1;
        const int nb  = cur ^ 1;

        // ---- wait for this warp's slice only; re-arm it ourselves ----
        if (t > 0 && kq != s) {
            const uint32_t mb = cur ? my_mb1 : my_mb0;
            mbar_wait(mb, (uint32_t)(cur ? ph1 : ph0));
            if (uh == 0 && l == 0) mbar_expect_tx(mb, SLICE_BYTES);
        }
        if (t > 0) { if (cur) ph1 ^= 1; else ph0 ^= 1; }

        // ---- packed partial (h @ U) over this warp's k-slice, 4 batches ----
        unsigned long long a0 = 0ull, a1 = 0ull, a2 = 0ull, a3 = 0ull;
#pragma unroll
        for (int j = 0; j < 16; j++) {
            ulonglong2 h0 = *(const ulonglong2*)&hs[cur][kq][0][j * 4];  // warp-uniform
            ulonglong2 h1 = *(const ulonglong2*)&hs[cur][kq][1][j * 4];
            ulonglong2 h2 = *(const ulonglong2*)&hs[cur][kq][2][j * 4];
            ulonglong2 h3 = *(const ulonglong2*)&hs[cur][kq][3][j * 4];
            fma2(a0, h0.x, Urp[2 * j]);  fma2(a0, h0.y, Urp[2 * j + 1]);
            fma2(a1, h1.x, Urp[2 * j]);  fma2(a1, h1.y, Urp[2 * j + 1]);
            fma2(a2, h2.x, Urp[2 * j]);  fma2(a2, h2.y, Urp[2 * j + 1]);
            fma2(a3, h3.x, Urp[2 * j]);  fma2(a3, h3.y, Urp[2 * j + 1]);
        }

        ps[kq][0][ulocal] = sum2(a0);
        ps[kq][1][ulocal] = sum2(a1);
        ps[kq][2][ulocal] = sum2(a2);
        ps[kq][3][ulocal] = sum2(a3);
        __syncthreads();

        float hn = 0.0f;
        if (tid < 256) {
            float r = 0.0f;
#pragma unroll
            for (int w2 = 0; w2 < 8; w2++) r += ps[w2][eb][eul];
            const float hold = hs[cur][s][eb][eul];
            hn = fmaf(aa, hold, invt * (r + xw + bi));
            if (t + 1 < SEQ) hs[nb][s][eb][eul] = hn;   // own slice local
        }
        __syncthreads();                     // slice complete before push

        if (t + 1 < SEQ && tid < 8 && tid != s) {
            fence_async_();
            const uint32_t src = nb ? slice1 : slice0;
            const uint32_t dst = mapa_u32(src, tid);
            const uint32_t mb  = mapa_u32(mbar_base + (uint32_t)(nb * 8 + s) * 8, tid);
            bulk_s2s(dst, src, SLICE_BYTES, mb);
        }

        if (tid < 256) {
            orow[(size_t)t * UNITS] = hn;
            if (t + 1 < SEQ) xw = __ldg(orow + (size_t)(t + 1) * UNITS);
        }
    }

    cluster_sync_();                         // no CTA exits with peers' DMAs pending
}

// =============================== launch ======================================
extern "C" void kernel_launch(void* const* d_in, const int* in_sizes, int n_in,
                              void* d_out, int out_size) {
    const float* x    = (const float*)d_in[0];   // [64,1024,256]
    const float* W    = (const float*)d_in[1];   // [256,512]
    const float* U    = (const float*)d_in[2];   // [512,512]
    const float* bias = (const float*)d_in[3];   // [512]
    const float* tau  = (const float*)d_in[4];   // [512]
    float* out = (float*)d_out;                  // [64,1024,512]

    dim3 ggrid(UNITS / GM_TN, (BATCH * SEQ) / GM_TM);   // (4, 512)
    xw_gemm_kernel<<<ggrid, 256>>>(x, W, out);

    ltc_scan_kernel<<<SCAN_CTAS, 512>>>(U, bias, tau, out);
}

// round 7
// speedup vs baseline: 1.2278x; 1.2278x over previous
#include <cuda_runtime.h>
#include <cstdint>

#define BATCH 64
#define SEQ   1024
#define DIN   256
#define UNITS 512

__device__ __forceinline__ void fma2(unsigned long long& d, unsigned long long a,
                                     unsigned long long b) {
    asm("fma.rn.f32x2 %0, %1, %2, %0;" : "+l"(d) : "l"(a), "l"(b));
}
__device__ __forceinline__ unsigned long long pack2(float x, float y) {
    unsigned long long r;
    asm("mov.b64 %0, {%1, %2};" : "=l"(r) : "f"(x), "f"(y));
    return r;
}
__device__ __forceinline__ float sum2(unsigned long long p) {
    float lo, hi;
    asm("mov.b64 {%0, %1}, %2;" : "=f"(lo), "=f"(hi) : "l"(p));
    return lo + hi;
}

// ================= xW GEMM: C[65536,512] = X[65536,256] @ W[256,512] ==========
#define GM_TM 128
#define GM_TN 128
#define GM_TK 16

__global__ void __launch_bounds__(256) xw_gemm_kernel(const float* __restrict__ X,
                                                      const float* __restrict__ W,
                                                      float* __restrict__ C) {
    __shared__ float As[GM_TK][GM_TM + 4];   // transposed: As[k][m]
    __shared__ float Bs[GM_TK][GM_TN + 4];

    const int tid = threadIdx.x;
    const int bm = blockIdx.y * GM_TM;
    const int bn = blockIdx.x * GM_TN;
    const int tx = tid & 15;
    const int ty = tid >> 4;

    unsigned long long acc2[8][4];
#pragma unroll
    for (int i = 0; i < 8; i++)
#pragma unroll
        for (int j = 0; j < 4; j++) acc2[i][j] = 0ull;

    const int arow = tid >> 2;
    const int acol = (tid & 3) * 4;
    const int brow = tid >> 5;
    const int bcol = (tid & 31) * 4;

    for (int k0 = 0; k0 < DIN; k0 += GM_TK) {
#pragma unroll
        for (int p = 0; p < 2; p++) {
            float4 v = *(const float4*)&X[(size_t)(bm + arow + p * 64) * DIN + k0 + acol];
            As[acol + 0][arow + p * 64] = v.x;
            As[acol + 1][arow + p * 64] = v.y;
            As[acol + 2][arow + p * 64] = v.z;
            As[acol + 3][arow + p * 64] = v.w;
        }
#pragma unroll
        for (int p = 0; p < 2; p++) {
            *(float4*)&Bs[brow + p * 8][bcol] =
                *(const float4*)&W[(size_t)(k0 + brow + p * 8) * UNITS + bn + bcol];
        }
        __syncthreads();

#pragma unroll
        for (int kk = 0; kk < GM_TK; kk++) {
            float a[8];
            *(float4*)&a[0] = *(const float4*)&As[kk][ty * 8];
            *(float4*)&a[4] = *(const float4*)&As[kk][ty * 8 + 4];
            unsigned long long bp[4];
            *(ulonglong2*)&bp[0] = *(const ulonglong2*)&Bs[kk][tx * 8];
            *(ulonglong2*)&bp[2] = *(const ulonglong2*)&Bs[kk][tx * 8 + 4];
#pragma unroll
            for (int i = 0; i < 8; i++) {
                const unsigned long long av = pack2(a[i], a[i]);
                fma2(acc2[i][0], av, bp[0]);
                fma2(acc2[i][1], av, bp[1]);
                fma2(acc2[i][2], av, bp[2]);
                fma2(acc2[i][3], av, bp[3]);
            }
        }
        __syncthreads();
    }

#pragma unroll
    for (int i = 0; i < 8; i++) {
        size_t row = (size_t)(bm + ty * 8 + i) * UNITS + bn + tx * 8;
        ulonglong2 v0, v1;
        v0.x = acc2[i][0]; v0.y = acc2[i][1];
        v1.x = acc2[i][2]; v1.y = acc2[i][3];
        *(ulonglong2*)&C[row]     = v0;
        *(ulonglong2*)&C[row + 4] = v1;
    }
}

// ================= LTC scan: clusters of 8, per-slice mbarriers ==============
// Cluster c owns batches [4c,4c+4). Rank s owns units [64s,64s+64).
// 256 threads, 8 warps: warp w owns k-slice [64w,64w+64) and reads only
// hs[.][w][.][.]; it waits ONLY slice w's mbar (skip if w==s) and re-arms it.
// Lane owns a u-pair. Exchange: 7x 1KB cp.async.bulk to peers.
#define CLUSTER_SZ 8
#define SCAN_CTAS 128
#define SLICE_BYTES 1024

__device__ __forceinline__ void cluster_sync_() {
    asm volatile("barrier.cluster.arrive.aligned;" ::: "memory");
    asm volatile("barrier.cluster.wait.aligned;"   ::: "memory");
}
__device__ __forceinline__ uint32_t mapa_u32(uint32_t addr, int rank) {
    uint32_t r;
    asm("mapa.shared::cluster.u32 %0, %1, %2;" : "=r"(r) : "r"(addr), "r"(rank));
    return r;
}
__device__ __forceinline__ void mbar_init(uint32_t mbar, uint32_t count) {
    asm volatile("mbarrier.init.shared.b64 [%0], %1;" :: "r"(mbar), "r"(count) : "memory");
}
__device__ __forceinline__ void mbar_expect_tx(uint32_t mbar, uint32_t bytes) {
    asm volatile("mbarrier.arrive.expect_tx.shared.b64 _, [%0], %1;"
                 :: "r"(mbar), "r"(bytes) : "memory");
}
__device__ __forceinline__ void mbar_wait(uint32_t mbar, uint32_t parity) {
    asm volatile(
        "{\n\t"
        ".reg .pred P1;\n\t"
        "WAIT_LOOP_%=:\n\t"
        "mbarrier.try_wait.parity.acquire.cta.shared::cta.b64 P1, [%0], %1, 0x989680;\n\t"
        "@P1 bra.uni WAIT_DONE_%=;\n\t"
        "bra.uni WAIT_LOOP_%=;\n\t"
        "WAIT_DONE_%=:\n\t"
        "}"
        :: "r"(mbar), "r"(parity) : "memory");
}
__device__ __forceinline__ void bulk_s2s(uint32_t dst_cluster, uint32_t src_cta,
                                         uint32_t bytes, uint32_t mbar_cluster) {
    asm volatile(
        "cp.async.bulk.shared::cluster.shared::cta.mbarrier::complete_tx::bytes "
        "[%0], [%1], %2, [%3];"
        :: "r"(dst_cluster), "r"(src_cta), "r"(bytes), "r"(mbar_cluster) : "memory");
}
__device__ __forceinline__ void fence_async_() {
    asm volatile("fence.proxy.async.shared::cta;" ::: "memory");
}

__global__ void __launch_bounds__(256, 1) __cluster_dims__(CLUSTER_SZ, 1, 1)
ltc_scan_kernel(const float* __restrict__ U,
                const float* __restrict__ bias,
                const float* __restrict__ tau,
                float* out) {
    __shared__ __align__(128) float hs[2][8][4][64];   // [buf][slice][batch][u_local]
    __shared__ float ps[8][4][68];                     // k-split partials
    __shared__ __align__(8) unsigned long long mbar[2][8];   // [buf][slice]

    const int tid = threadIdx.x;
    const int w   = tid >> 5;               // warp -> k-slice (reads hs[.][w][.][.])
    const int l   = tid & 31;
    const int cta = blockIdx.x;
    const int s   = cta & 7;                // cluster rank = unit slice
    const int b0  = (cta >> 3) * 4;
    const int u0  = s * 64 + 2 * l;

    // ---- U slice in packed registers: Urp0/1[p] = {U[k][u],U[k+1][u]}, k=w*64+2p
    unsigned long long Urp0[32], Urp1[32];
#pragma unroll
    for (int p = 0; p < 32; p++) {
        const int k = w * 64 + 2 * p;
        float2 va = *(const float2*)&U[(size_t)k * UNITS + u0];
        float2 vb = *(const float2*)&U[(size_t)(k + 1) * UNITS + u0];
        Urp0[p] = pack2(va.x, vb.x);
        Urp1[p] = pack2(va.y, vb.y);
    }

    // ---- epilogue mapping ----
    const int eb  = tid >> 6;               // 0..3
    const int eul = tid & 63;               // 0..63
    const int eu  = s * 64 + eul;
    const float invt = 1.0f / tau[eu];
    const float aa   = 1.0f - invt;
    const float bi   = bias[eu];
    float* orow = out + (size_t)(b0 + eb) * SEQ * UNITS + eu;

    // ---- zero h0 buffer ----
    for (int i = tid; i < 8 * 4 * 64; i += 256) ((float*)hs[0])[i] = 0.0f;

    const uint32_t mbar_base = (uint32_t)__cvta_generic_to_shared(&mbar[0][0]);
    const uint32_t slice0 = (uint32_t)__cvta_generic_to_shared(&hs[0][s][0][0]);
    const uint32_t slice1 = (uint32_t)__cvta_generic_to_shared(&hs[1][s][0][0]);

    if (tid < 16) {                          // (buf = tid>>3, slice = tid&7)
        const int sl = tid & 7;
        if (sl != s) {                       // own slice never arrives via DMA
            const uint32_t mb = mbar_base + (uint32_t)tid * 8;
            mbar_init(mb, 1);
            mbar_expect_tx(mb, SLICE_BYTES);
        }
    }
    __syncthreads();
    cluster_sync_();                         // mbars + h0 visible cluster-wide

    float xw = __ldg(orow);                  // prefetch xW for t=0
    int ph0 = 0, ph1 = 0;
    const uint32_t my_mb0 = mbar_base + (uint32_t)w * 8;        // buf0, slice w
    const uint32_t my_mb1 = mbar_base + (uint32_t)(8 + w) * 8;  // buf1, slice w

    for (int t = 0; t < SEQ; t++) {
        const int cur = t & 1;
        const int nb  = cur ^ 1;

        // ---- wait only this warp's slice; re-arm it ourselves ----
        if (t > 0 && w != s) {
            const uint32_t mb = cur ? my_mb1 : my_mb0;
            mbar_wait(mb, (uint32_t)(cur ? ph1 : ph0));
            if (l == 0) mbar_expect_tx(mb, SLICE_BYTES);   // re-arm for fill at t+1
        }
        if (t > 0) { if (cur) ph1 ^= 1; else ph0 ^= 1; }

        // ---- packed partial (h @ U) over this warp's k-slice, 4 batches ----
        unsigned long long a00 = 0ull, a01 = 0ull, a10 = 0ull, a11 = 0ull;
        unsigned long long a20 = 0ull, a21 = 0ull, a30 = 0ull, a31 = 0ull;
#pragma unroll
        for (int j = 0; j < 16; j++) {
            ulonglong2 h0 = *(const ulonglong2*)&hs[cur][w][0][j * 4];  // warp-uniform
            ulonglong2 h1 = *(const ulonglong2*)&hs[cur][w][1][j * 4];
            ulonglong2 h2 = *(const ulonglong2*)&hs[cur][w][2][j * 4];
            ulonglong2 h3 = *(const ulonglong2*)&hs[cur][w][3][j * 4];
            fma2(a00, h0.x, Urp0[2 * j]);  fma2(a00, h0.y, Urp0[2 * j + 1]);
            fma2(a01, h0.x, Urp1[2 * j]);  fma2(a01, h0.y, Urp1[2 * j + 1]);
            fma2(a10, h1.x, Urp0[2 * j]);  fma2(a10, h1.y, Urp0[2 * j + 1]);
            fma2(a11, h1.x, Urp1[2 * j]);  fma2(a11, h1.y, Urp1[2 * j + 1]);
            fma2(a20, h2.x, Urp0[2 * j]);  fma2(a20, h2.y, Urp0[2 * j + 1]);
            fma2(a21, h2.x, Urp1[2 * j]);  fma2(a21, h2.y, Urp1[2 * j + 1]);
            fma2(a30, h3.x, Urp0[2 * j]);  fma2(a30, h3.y, Urp0[2 * j + 1]);
            fma2(a31, h3.x, Urp1[2 * j]);  fma2(a31, h3.y, Urp1[2 * j + 1]);
        }

        *(float2*)&ps[w][0][2 * l] = make_float2(sum2(a00), sum2(a01));
        *(float2*)&ps[w][1][2 * l] = make_float2(sum2(a10), sum2(a11));
        *(float2*)&ps[w][2][2 * l] = make_float2(sum2(a20), sum2(a21));
        *(float2*)&ps[w][3][2 * l] = make_float2(sum2(a30), sum2(a31));
        __syncthreads();

        // ---- reduce across 8 warps; epilogue ----
        float r = 0.0f;
#pragma unroll
        for (int w2 = 0; w2 < 8; w2++) r += ps[w2][eb][eul];

        const float hold = hs[cur][s][eb][eul];
        const float hn = fmaf(aa, hold, invt * (r + xw + bi));

        if (t + 1 < SEQ) {
            hs[nb][s][eb][eul] = hn;         // own slice stays local
            __syncthreads();                 // slice complete
            if (tid < 8 && tid != s) {       // push 1KB slice to 7 peers
                fence_async_();
                const uint32_t src = nb ? slice1 : slice0;
                const uint32_t dst = mapa_u32(src, tid);
                const uint32_t mb  = mapa_u32(mbar_base + (uint32_t)(nb * 8 + s) * 8, tid);
                bulk_s2s(dst, src, SLICE_BYTES, mb);
            }
        }

        // off the inter-CTA critical path:
        orow[(size_t)t * UNITS] = hn;
        if (t + 1 < SEQ) xw = __ldg(orow + (size_t)(t + 1) * UNITS);
    }

    cluster_sync_();                         // no CTA exits with peers' DMAs pending
}

// =============================== launch ======================================
extern "C" void kernel_launch(void* const* d_in, const int* in_sizes, int n_in,
                              void* d_out, int out_size) {
    const float* x    = (const float*)d_in[0];   // [64,1024,256]
    const float* W    = (const float*)d_in[1];   // [256,512]
    const float* U    = (const float*)d_in[2];   // [512,512]
    const float* bias = (const float*)d_in[3];   // [512]
    const float* tau  = (const float*)d_in[4];   // [512]
    float* out = (float*)d_out;                  // [64,1024,512]

    dim3 ggrid(UNITS / GM_TN, (BATCH * SEQ) / GM_TM);   // (4, 512)
    xw_gemm_kernel<<<ggrid, 256>>>(x, W, out);

    ltc_scan_kernel<<<SCAN_CTAS, 256>>>(U, bias, tau, out);
}